// round 13
// baseline (speedup 1.0000x reference)
#include <cuda_runtime.h>
#include <cstdint>

#define N_PTS      16384
#define B_SZ       4
#define S_SAMPLES  1024
#define K_NB       32
#define C_FEAT     128

#define CEN_OFF    0
#define GX_OFF     (B_SZ * S_SAMPLES * 3)                      // 12288
#define GF_OFF     (GX_OFF + B_SZ * S_SAMPLES * K_NB * 3)     // 405504

#define FPS_T      512                  // 16 warps (issue-bound fixed phases)
#define N_GRP      256                  // groups of 64 sorted points
#define GRP_SZ     64
#define N_CELLS    512                  // 8x8x8 spatial grid

typedef unsigned long long ull;

// Initial group key: value = 1e10f (reference init), index payload = 0.
// Hi bits MUST be a finite float (NaN kills the prune compare — R5 bug).
#define KEY_INIT   ((ull)0x501502F9u << 32)    // __float_as_uint(1e10f) << 32

// ---------------- spatially sorted points (device globals: no allocs) -------
// float4 = (x, y, z, bitcast original index)
__device__ float4 g_pts[B_SZ * N_PTS];

__device__ __forceinline__ int cell_of(float x, float y, float z) {
    int cx = min(max((int)(x * 8.0f), 0), 7);
    int cy = min(max((int)(y * 8.0f), 0), 7);
    int cz = min(max((int)(z * 8.0f), 0), 7);
    return (cx << 6) | (cy << 3) | cz;
}

// ============================================================================
// Counting sort by 8x8x8 cell. One CTA (1024 thr) per batch. In-cell order is
// nondeterministic (atomics) but FPS output is order-independent (order-free
// min updates + order-free (value, first-original-index) argmax).
// ============================================================================
__global__ __launch_bounds__(1024)
void sort_kernel(const float* __restrict__ xyz)
{
    __shared__ int hist[N_CELLS];
    __shared__ int wsum[16];
    const int t = threadIdx.x;
    const int b = blockIdx.x;
    const float* base = xyz + (size_t)b * N_PTS * 3;

    if (t < N_CELLS) hist[t] = 0;
    __syncthreads();
    for (int i = t; i < N_PTS; i += 1024)
        atomicAdd(&hist[cell_of(base[3 * i], base[3 * i + 1], base[3 * i + 2])], 1);
    __syncthreads();

    int incl = 0, own = 0;
    const int lane = t & 31, w = t >> 5;
    if (t < N_CELLS) {
        own = hist[t];
        incl = own;
#pragma unroll
        for (int off = 1; off < 32; off <<= 1) {
            int n = __shfl_up_sync(0xFFFFFFFFu, incl, off);
            if (lane >= off) incl += n;
        }
        if (lane == 31) wsum[w] = incl;
    }
    __syncthreads();
    if (t < 32) {
        int v = (t < 16) ? wsum[t] : 0;
#pragma unroll
        for (int off = 1; off < 16; off <<= 1) {
            int n = __shfl_up_sync(0xFFFFFFFFu, v, off);
            if (t >= off) v += n;
        }
        if (t < 16) wsum[t] = v;        // inclusive warp sums
    }
    __syncthreads();
    if (t < N_CELLS) hist[t] = incl - own + (w ? wsum[w - 1] : 0);  // exclusive
    __syncthreads();
    for (int i = t; i < N_PTS; i += 1024) {
        const float x = base[3 * i], y = base[3 * i + 1], z = base[3 * i + 2];
        const int pos = atomicAdd(&hist[cell_of(x, y, z)], 1);
        g_pts[b * N_PTS + pos] = make_float4(x, y, z, __int_as_float(i));
    }
}

// ============================================================================
// Task-parallel pruned FPS (R12 architecture — measured best — at 512 threads:
// halves the issue cost of the fixed per-iteration phases).
//  P1: thread t (<256) prunes its 64-pt group via round-down BB bound vs
//      cached group-key ub; active groups compacted (ballot + 16-count scan).
//  P2: one warp per active task (16 warps), TWO points per lane.
//  P3: CTA argmax: 16 warp partials + redundant reduce in every warp.
// Exactness: identical rn distance chain; prune skips only provably
// non-improving updates (1e-5 margin >> 4-ulp rn under-rounding); the
// (max value, first-original-index) argmax is scan-order-free.
// ============================================================================
extern __shared__ float fps_md[];        // min_d[16384]

__global__ __launch_bounds__(FPS_T, 1)
void fps_kernel(const float* __restrict__ xyz, float* __restrict__ out)
{
    __shared__ ull s_key[N_GRP];
    __shared__ ull s_wkey[16];
    __shared__ int s_act[N_GRP];
    __shared__ int s_wcnt[16];

    const int t = threadIdx.x;
    const int b = blockIdx.x;
    const int lane = t & 31, w = t >> 5;
    float* cen = out + CEN_OFF + (size_t)b * S_SAMPLES * 3;
    const float* obase = xyz + (size_t)b * N_PTS * 3;
    const float4* pbase = g_pts + b * N_PTS;

    // ---- setup: 64-pt group BB in registers of thread t<256 ----
    float blx = 1e30f, bly = 1e30f, blz = 1e30f;
    float bhx = -1e30f, bhy = -1e30f, bhz = -1e30f;
    if (t < N_GRP) {
#pragma unroll 4
        for (int j = 0; j < GRP_SZ; ++j) {
            const float4 p = __ldg(&pbase[t * GRP_SZ + j]);
            blx = fminf(blx, p.x); bhx = fmaxf(bhx, p.x);
            bly = fminf(bly, p.y); bhy = fmaxf(bhy, p.y);
            blz = fminf(blz, p.z); bhz = fmaxf(bhz, p.z);
        }
        s_key[t] = KEY_INIT;
    }
#pragma unroll
    for (int j = 0; j < N_PTS / FPS_T; ++j)
        fps_md[j * FPS_T + t] = 1e10f;

    float cx = __ldg(obase + 0), cy = __ldg(obase + 1), cz = __ldg(obase + 2);
    if (t == 0) { cen[0] = cx; cen[1] = cy; cen[2] = cz; }
    __syncthreads();

    for (int s = 1; s < S_SAMPLES; ++s) {
        // ---- P1: prune + ballot (warps 0-7 own groups; 8-15 idle-cheap) ----
        bool active = false;
        if (t < N_GRP) {
            const float dx = fmaxf(fmaxf(__fsub_rd(blx, cx), __fsub_rd(cx, bhx)), 0.0f);
            const float dy = fmaxf(fmaxf(__fsub_rd(bly, cy), __fsub_rd(cy, bhy)), 0.0f);
            const float dz = fmaxf(fmaxf(__fsub_rd(blz, cz), __fsub_rd(cz, bhz)), 0.0f);
            const float lb2 = __fadd_rd(__fadd_rd(__fmul_rd(dx, dx), __fmul_rd(dy, dy)),
                                        __fmul_rd(dz, dz));
            const float ub = __uint_as_float((unsigned)(s_key[t] >> 32));
            active = (__fmul_rd(lb2, 0.99999f) < ub);
        }
        const unsigned mask = __ballot_sync(0xFFFFFFFFu, active);
        if (lane == 0 && w < 8) s_wcnt[w] = __popc(mask);
        else if (lane == 0) s_wcnt[w] = 0;
        __syncthreads();                                   // (1)

        // redundant per-warp scan of the 16 warp counts -> compaction offsets
        int v = (lane < 16) ? s_wcnt[lane] : 0;
#pragma unroll
        for (int off = 1; off < 16; off <<= 1) {
            int n = __shfl_up_sync(0xFFFFFFFFu, v, off);
            if (lane >= off) v += n;
        }
        const int A = __shfl_sync(0xFFFFFFFFu, v, 15);
        const int wbase = (w == 0) ? 0 : __shfl_sync(0xFFFFFFFFu, v, w - 1);
        if (active)
            s_act[wbase + __popc(mask & ((1u << lane) - 1u))] = t;
        __syncthreads();                                   // (2)

        // ---- P2: warp per active 64-pt group, two points per lane ----
        for (int task = w; task < A; task += 16) {
            const int g = s_act[task];
            const int i0 = g * GRP_SZ + lane;
            const int i1 = i0 + 32;
            const float4 p0 = __ldg(&pbase[i0]);
            const float4 p1 = __ldg(&pbase[i1]);

            const float dx0 = __fadd_rn(p0.x, -cx);
            const float dy0 = __fadd_rn(p0.y, -cy);
            const float dz0 = __fadd_rn(p0.z, -cz);
            const float d20 = __fadd_rn(__fadd_rn(__fmul_rn(dx0, dx0),
                                                  __fmul_rn(dy0, dy0)),
                                        __fmul_rn(dz0, dz0));
            const float dx1 = __fadd_rn(p1.x, -cx);
            const float dy1 = __fadd_rn(p1.y, -cy);
            const float dz1 = __fadd_rn(p1.z, -cz);
            const float d21 = __fadd_rn(__fadd_rn(__fmul_rn(dx1, dx1),
                                                  __fmul_rn(dy1, dy1)),
                                        __fmul_rn(dz1, dz1));
            const float m0 = fminf(fps_md[i0], d20);
            fps_md[i0] = m0;
            const float m1 = fminf(fps_md[i1], d21);
            fps_md[i1] = m1;

            // within-lane pair max with exact min-sid tie select
            const unsigned vb0 = __float_as_uint(m0);   // md>=0: bit-monotone
            const unsigned vb1 = __float_as_uint(m1);
            const int s0 = __float_as_int(p0.w);
            const int s1 = __float_as_int(p1.w);
            const unsigned lv = (vb0 >= vb1) ? vb0 : vb1;
            int sel;
            if (vb0 == vb1)      sel = min(s0, s1);
            else if (vb0 == lv)  sel = s0;
            else                 sel = s1;

            const unsigned vmax = __reduce_max_sync(0xFFFFFFFFu, lv);
            const unsigned cand = (lv == vmax)
                ? (0xFFFFFFFFu - (unsigned)sel) : 0u;
            const unsigned im = __reduce_max_sync(0xFFFFFFFFu, cand);
            if (lane == 0) s_key[g] = ((ull)vmax << 32) | im;
        }
        __syncthreads();                                   // (3)

        // ---- P3: CTA argmax over 256 group keys (t<256 reads one each) ----
        const ull key = (t < N_GRP) ? s_key[t] : 0ull;
        const unsigned hi = (unsigned)(key >> 32), lo = (unsigned)key;
        const unsigned wv = __reduce_max_sync(0xFFFFFFFFu, hi);
        const unsigned wl = __reduce_max_sync(0xFFFFFFFFu, (hi == wv) ? lo : 0u);
        if (lane == 0 && w < 8) s_wkey[w] = ((ull)wv << 32) | wl;
        else if (lane == 0) s_wkey[w] = 0ull;
        __syncthreads();                                   // (4)

        const ull k2 = s_wkey[lane & 15];                   // 16 partials (dup ok)
        const unsigned h2 = (unsigned)(k2 >> 32), l2 = (unsigned)k2;
        const unsigned gv = __reduce_max_sync(0xFFFFFFFFu, h2);
        const unsigned gl = __reduce_max_sync(0xFFFFFFFFu, (h2 == gv) ? l2 : 0u);

        const int widx = (int)(0xFFFFFFFFu - gl);
        cx = __ldg(obase + widx * 3 + 0);                   // broadcast, L1-hot
        cy = __ldg(obase + widx * 3 + 1);
        cz = __ldg(obase + widx * 3 + 2);
        if (t == 0) { cen[s * 3 + 0] = cx; cen[s * 3 + 1] = cy; cen[s * 3 + 2] = cz; }
    }
}

// ============================================================================
// Ball query + gather: one warp per centroid, 64 pts per ballot iteration,
// early exit at K hits. First 2048 points cached in SMEM per block; gmem tail.
// Scan order == ascending index == reference top_k order.
// ============================================================================
#define BQ_WARPS   8
#define BQ_CACHE   2048

__global__ __launch_bounds__(BQ_WARPS * 32)
void group_kernel(const float* __restrict__ xyz,
                  const float* __restrict__ feat,
                  float* __restrict__ out)
{
    __shared__ float s_pts[BQ_CACHE * 3];
    __shared__ int   s_idx[BQ_WARPS][K_NB];

    const int tid  = threadIdx.x;
    const int w    = tid >> 5;
    const int lane = tid & 31;
    const int c    = blockIdx.x * BQ_WARPS + w;          // centroid id
    const int b    = c >> 10;                            // 128 blocks per batch
    const float* base = xyz + (size_t)b * N_PTS * 3;

    for (int i = tid; i < BQ_CACHE * 3; i += BQ_WARPS * 32) s_pts[i] = base[i];
    __syncthreads();

    const float* cen = out + CEN_OFF + (size_t)c * 3;
    const float cx = __ldg(cen + 0), cy = __ldg(cen + 1), cz = __ldg(cen + 2);
    const float R2 = (float)(0.2 * 0.2);

    int cnt = 0;
    for (int j = 0; j < BQ_CACHE / 64 && cnt < K_NB; ++j) {
        const int p0 = j * 64 + lane;
        const int p1 = p0 + 32;
        const float dx0 = __fadd_rn(cx, -s_pts[p0 * 3 + 0]);
        const float dy0 = __fadd_rn(cy, -s_pts[p0 * 3 + 1]);
        const float dz0 = __fadd_rn(cz, -s_pts[p0 * 3 + 2]);
        const float sq0 = __fadd_rn(__fadd_rn(__fmul_rn(dx0, dx0), __fmul_rn(dy0, dy0)),
                                    __fmul_rn(dz0, dz0));
        const float dx1 = __fadd_rn(cx, -s_pts[p1 * 3 + 0]);
        const float dy1 = __fadd_rn(cy, -s_pts[p1 * 3 + 1]);
        const float dz1 = __fadd_rn(cz, -s_pts[p1 * 3 + 2]);
        const float sq1 = __fadd_rn(__fadd_rn(__fmul_rn(dx1, dx1), __fmul_rn(dy1, dy1)),
                                    __fmul_rn(dz1, dz1));
        const bool h0 = (sq0 <= R2);
        const bool h1 = (sq1 <= R2);
        const unsigned m0 = __ballot_sync(0xFFFFFFFFu, h0);
        const unsigned m1 = __ballot_sync(0xFFFFFFFFu, h1);
        if (h0) {
            const int pos = cnt + __popc(m0 & ((1u << lane) - 1u));
            if (pos < K_NB) s_idx[w][pos] = p0;
        }
        const int c1 = cnt + __popc(m0);
        if (h1) {
            const int pos = c1 + __popc(m1 & ((1u << lane) - 1u));
            if (pos < K_NB) s_idx[w][pos] = p1;
        }
        cnt = c1 + __popc(m1);
    }
    for (int j = BQ_CACHE / 64; j < N_PTS / 64 && cnt < K_NB; ++j) {
        const int p0 = j * 64 + lane;
        const int p1 = p0 + 32;
        const float dx0 = __fadd_rn(cx, -base[p0 * 3 + 0]);
        const float dy0 = __fadd_rn(cy, -base[p0 * 3 + 1]);
        const float dz0 = __fadd_rn(cz, -base[p0 * 3 + 2]);
        const float sq0 = __fadd_rn(__fadd_rn(__fmul_rn(dx0, dx0), __fmul_rn(dy0, dy0)),
                                    __fmul_rn(dz0, dz0));
        const float dx1 = __fadd_rn(cx, -base[p1 * 3 + 0]);
        const float dy1 = __fadd_rn(cy, -base[p1 * 3 + 1]);
        const float dz1 = __fadd_rn(cz, -base[p1 * 3 + 2]);
        const float sq1 = __fadd_rn(__fadd_rn(__fmul_rn(dx1, dx1), __fmul_rn(dy1, dy1)),
                                    __fmul_rn(dz1, dz1));
        const bool h0 = (sq0 <= R2);
        const bool h1 = (sq1 <= R2);
        const unsigned m0 = __ballot_sync(0xFFFFFFFFu, h0);
        const unsigned m1 = __ballot_sync(0xFFFFFFFFu, h1);
        if (h0) {
            const int pos = cnt + __popc(m0 & ((1u << lane) - 1u));
            if (pos < K_NB) s_idx[w][pos] = p0;
        }
        const int c1 = cnt + __popc(m0);
        if (h1) {
            const int pos = c1 + __popc(m1 & ((1u << lane) - 1u));
            if (pos < K_NB) s_idx[w][pos] = p1;
        }
        cnt = c1 + __popc(m1);
    }
    __syncwarp();
    const int first = s_idx[w][0];          // >=1 hit guaranteed (centroid itself)
    if (cnt < K_NB && lane >= cnt) s_idx[w][lane] = first;
    __syncwarp();

    {
        const int gi = s_idx[w][lane];
        float* go = out + GX_OFF + ((size_t)c * K_NB + lane) * 3;
        go[0] = __fadd_rn(base[gi * 3 + 0], -cx);
        go[1] = __fadd_rn(base[gi * 3 + 1], -cy);
        go[2] = __fadd_rn(base[gi * 3 + 2], -cz);
    }

    const float4* f4 = (const float4*)feat;
    float4* o4 = (float4*)(out + GF_OFF) + (size_t)c * K_NB * (C_FEAT / 4);
#pragma unroll 4
    for (int k = 0; k < K_NB; ++k) {
        const int gi = s_idx[w][k];
        o4[(size_t)k * (C_FEAT / 4) + lane] =
            f4[((size_t)b * N_PTS + gi) * (C_FEAT / 4) + lane];
    }
}

// ============================================================================
extern "C" void kernel_launch(void* const* d_in, const int* in_sizes, int n_in,
                              void* d_out, int out_size)
{
    const float* xyz  = (const float*)d_in[0];
    const float* feat = (const float*)d_in[1];
    if (n_in >= 2 && in_sizes[0] > in_sizes[1]) {   // defensive: xyz is smaller
        const float* tmp = xyz; xyz = feat; feat = tmp;
    }
    float* out = (float*)d_out;

    const int fps_smem = N_PTS * 4;     // min_d
    cudaFuncSetAttribute(fps_kernel, cudaFuncAttributeMaxDynamicSharedMemorySize,
                         fps_smem);

    sort_kernel<<<B_SZ, 1024>>>(xyz);
    fps_kernel<<<B_SZ, FPS_T, fps_smem>>>(xyz, out);
    group_kernel<<<(B_SZ * S_SAMPLES) / BQ_WARPS, BQ_WARPS * 32>>>(xyz, feat, out);
}

// round 14
// speedup vs baseline: 1.0242x; 1.0242x over previous
#include <cuda_runtime.h>
#include <cstdint>

#define N_PTS      16384
#define B_SZ       4
#define S_SAMPLES  1024
#define K_NB       32
#define C_FEAT     128

#define CEN_OFF    0
#define GX_OFF     (B_SZ * S_SAMPLES * 3)                      // 12288
#define GF_OFF     (GX_OFF + B_SZ * S_SAMPLES * K_NB * 3)     // 405504

#define FPS_T      1024                 // 32 warps (R12 measured best)
#define N_GRP      256                  // groups of 64 sorted points
#define GRP_SZ     64
#define N_CELLS    512                  // 8x8x8 spatial grid

typedef unsigned long long ull;

// Initial group key: value = 1e10f (reference init), index payload = 0.
// Hi bits MUST be a finite float (NaN kills the prune compare — R5 bug).
#define KEY_INIT   ((ull)0x501502F9u << 32)    // __float_as_uint(1e10f) << 32

// ---------------- spatially sorted points (device globals: no allocs) -------
// float4 = (x, y, z, bitcast original index)
__device__ float4 g_pts[B_SZ * N_PTS];

__device__ __forceinline__ int cell_of(float x, float y, float z) {
    int cx = min(max((int)(x * 8.0f), 0), 7);
    int cy = min(max((int)(y * 8.0f), 0), 7);
    int cz = min(max((int)(z * 8.0f), 0), 7);
    return (cx << 6) | (cy << 3) | cz;
}

// ============================================================================
// Counting sort by 8x8x8 cell. One CTA (1024 thr) per batch. In-cell order is
// nondeterministic (atomics) but FPS output is order-independent (order-free
// min updates + order-free (value, first-original-index) argmax).
// ============================================================================
__global__ __launch_bounds__(1024)
void sort_kernel(const float* __restrict__ xyz)
{
    __shared__ int hist[N_CELLS];
    __shared__ int wsum[16];
    const int t = threadIdx.x;
    const int b = blockIdx.x;
    const float* base = xyz + (size_t)b * N_PTS * 3;

    if (t < N_CELLS) hist[t] = 0;
    __syncthreads();
    for (int i = t; i < N_PTS; i += 1024)
        atomicAdd(&hist[cell_of(base[3 * i], base[3 * i + 1], base[3 * i + 2])], 1);
    __syncthreads();

    int incl = 0, own = 0;
    const int lane = t & 31, w = t >> 5;
    if (t < N_CELLS) {
        own = hist[t];
        incl = own;
#pragma unroll
        for (int off = 1; off < 32; off <<= 1) {
            int n = __shfl_up_sync(0xFFFFFFFFu, incl, off);
            if (lane >= off) incl += n;
        }
        if (lane == 31) wsum[w] = incl;
    }
    __syncthreads();
    if (t < 32) {
        int v = (t < 16) ? wsum[t] : 0;
#pragma unroll
        for (int off = 1; off < 16; off <<= 1) {
            int n = __shfl_up_sync(0xFFFFFFFFu, v, off);
            if (t >= off) v += n;
        }
        if (t < 16) wsum[t] = v;        // inclusive warp sums
    }
    __syncthreads();
    if (t < N_CELLS) hist[t] = incl - own + (w ? wsum[w - 1] : 0);  // exclusive
    __syncthreads();
    for (int i = t; i < N_PTS; i += 1024) {
        const float x = base[3 * i], y = base[3 * i + 1], z = base[3 * i + 2];
        const int pos = atomicAdd(&hist[cell_of(x, y, z)], 1);
        g_pts[b * N_PTS + pos] = make_float4(x, y, z, __int_as_float(i));
    }
}

// ============================================================================
// Task-parallel pruned FPS — R12 architecture (measured best) with P3 folded
// into P2 (contribution accounting) and an 8-wide compaction scan.
// THREE barriers/iter, zero atomics. One CTA (1024 thr = 32 warps)/batch.
//  P1: thread t (<256) reads its cached group key, prunes via round-down BB
//      bound; warps 0-7 publish activity counts. BARRIER 1.
//  scan: 8 counts, 3 shfls -> compaction offsets; active ids -> s_act.
//      BARRIER 2.
//  P2: one warp per active 64-pt group (2 pts/lane); per-task key via 2 REDUX
//      written to s_key; warp keeps running (val,idx) register max.
//  partial: running max merged with pruned-owned cached keys (2 REDUX) ->
//      s_wkey[w]. BARRIER 3. Redundant 32-partial argmax -> centroid LDG.
// Every group contributes exactly once (active -> processing warp; pruned ->
// owner's P1-read cached key). Exactness: identical rn distance chain; prune
// skips only provably non-improving updates (1e-5 margin >> 4-ulp rn
// under-rounding); (max value, first-orig-index) argmax is scan-order-free.
// ============================================================================
extern __shared__ float fps_md[];        // min_d[16384]

__global__ __launch_bounds__(FPS_T, 1)
void fps_kernel(const float* __restrict__ xyz, float* __restrict__ out)
{
    __shared__ ull s_key[N_GRP];
    __shared__ ull s_wkey[32];
    __shared__ int s_act[N_GRP];
    __shared__ int s_wcnt[8];

    const int t = threadIdx.x;
    const int b = blockIdx.x;
    const int lane = t & 31, w = t >> 5;
    float* cen = out + CEN_OFF + (size_t)b * S_SAMPLES * 3;
    const float* obase = xyz + (size_t)b * N_PTS * 3;
    const float4* pbase = g_pts + b * N_PTS;

    // ---- setup: 64-pt group BB in registers of thread t<256 ----
    float blx = 1e30f, bly = 1e30f, blz = 1e30f;
    float bhx = -1e30f, bhy = -1e30f, bhz = -1e30f;
    if (t < N_GRP) {
#pragma unroll 4
        for (int j = 0; j < GRP_SZ; ++j) {
            const float4 p = __ldg(&pbase[t * GRP_SZ + j]);
            blx = fminf(blx, p.x); bhx = fmaxf(bhx, p.x);
            bly = fminf(bly, p.y); bhy = fmaxf(bhy, p.y);
            blz = fminf(blz, p.z); bhz = fmaxf(bhz, p.z);
        }
        s_key[t] = KEY_INIT;
    }
#pragma unroll
    for (int j = 0; j < N_PTS / FPS_T; ++j)
        fps_md[j * FPS_T + t] = 1e10f;

    float cx = __ldg(obase + 0), cy = __ldg(obase + 1), cz = __ldg(obase + 2);
    if (t == 0) { cen[0] = cx; cen[1] = cy; cen[2] = cz; }
    __syncthreads();

    for (int s = 1; s < S_SAMPLES; ++s) {
        // ---- P1: prune + ballot (warps 0-7 own the 256 groups) ----
        bool active = false;
        ull mykey = 0;
        if (t < N_GRP) {
            mykey = s_key[t];                     // ordered by barrier 3 (s-1)
            const float dx = fmaxf(fmaxf(__fsub_rd(blx, cx), __fsub_rd(cx, bhx)), 0.0f);
            const float dy = fmaxf(fmaxf(__fsub_rd(bly, cy), __fsub_rd(cy, bhy)), 0.0f);
            const float dz = fmaxf(fmaxf(__fsub_rd(blz, cz), __fsub_rd(cz, bhz)), 0.0f);
            const float lb2 = __fadd_rd(__fadd_rd(__fmul_rd(dx, dx), __fmul_rd(dy, dy)),
                                        __fmul_rd(dz, dz));
            const float ub = __uint_as_float((unsigned)(mykey >> 32));
            active = (__fmul_rd(lb2, 0.99999f) < ub);
        }
        const unsigned mask = __ballot_sync(0xFFFFFFFFu, active);
        if (lane == 0 && w < 8) s_wcnt[w] = __popc(mask);
        __syncthreads();                                   // ---- BARRIER 1 ----

        // 8-wide scan (3 shfls) -> compaction offsets
        int v = (lane < 8) ? s_wcnt[lane] : 0;
#pragma unroll
        for (int off = 1; off < 8; off <<= 1) {
            int n = __shfl_up_sync(0xFFFFFFFFu, v, off);
            if (lane >= off) v += n;
        }
        const int A = __shfl_sync(0xFFFFFFFFu, v, 7);
        const int wbase = (w == 0) ? 0
                        : ((w < 8) ? __shfl_sync(0xFFFFFFFFu, v, w - 1) : 0);
        if (active)
            s_act[wbase + __popc(mask & ((1u << lane) - 1u))] = t;
        __syncthreads();                                   // ---- BARRIER 2 ----

        // ---- P2: warp per active 64-pt group; running register max ----
        unsigned rhi = 0u, rlo = 0u;
        for (int task = w; task < A; task += 32) {
            const int g = s_act[task];
            const int i0 = g * GRP_SZ + lane;
            const int i1 = i0 + 32;
            const float4 p0 = __ldg(&pbase[i0]);
            const float4 p1 = __ldg(&pbase[i1]);

            const float dx0 = __fadd_rn(p0.x, -cx);
            const float dy0 = __fadd_rn(p0.y, -cy);
            const float dz0 = __fadd_rn(p0.z, -cz);
            const float d20 = __fadd_rn(__fadd_rn(__fmul_rn(dx0, dx0),
                                                  __fmul_rn(dy0, dy0)),
                                        __fmul_rn(dz0, dz0));
            const float dx1 = __fadd_rn(p1.x, -cx);
            const float dy1 = __fadd_rn(p1.y, -cy);
            const float dz1 = __fadd_rn(p1.z, -cz);
            const float d21 = __fadd_rn(__fadd_rn(__fmul_rn(dx1, dx1),
                                                  __fmul_rn(dy1, dy1)),
                                        __fmul_rn(dz1, dz1));
            const float m0 = fminf(fps_md[i0], d20);
            fps_md[i0] = m0;
            const float m1 = fminf(fps_md[i1], d21);
            fps_md[i1] = m1;

            // within-lane pair max with exact min-sid tie select
            const unsigned vb0 = __float_as_uint(m0);   // md>=0: bit-monotone
            const unsigned vb1 = __float_as_uint(m1);
            const int s0 = __float_as_int(p0.w);
            const int s1 = __float_as_int(p1.w);
            const unsigned lv = (vb0 >= vb1) ? vb0 : vb1;
            int sel;
            if (vb0 == vb1)      sel = min(s0, s1);
            else if (vb0 == lv)  sel = s0;
            else                 sel = s1;

            const unsigned vmax = __reduce_max_sync(0xFFFFFFFFu, lv);
            const unsigned cand = (lv == vmax)
                ? (0xFFFFFFFFu - (unsigned)sel) : 0u;
            const unsigned im = __reduce_max_sync(0xFFFFFFFFu, cand);
            if (lane == 0) s_key[g] = ((ull)vmax << 32) | im;
            if (vmax > rhi || (vmax == rhi && im > rlo)) { rhi = vmax; rlo = im; }
        }

        // ---- warp partial: running max + pruned-owned cached keys ----
        const unsigned chi = (t < N_GRP && !active) ? (unsigned)(mykey >> 32) : 0u;
        const unsigned clo = (t < N_GRP && !active) ? (unsigned)mykey : 0u;
        unsigned wh = __reduce_max_sync(0xFFFFFFFFu, chi);
        unsigned wl = __reduce_max_sync(0xFFFFFFFFu, (chi == wh) ? clo : 0u);
        if (rhi > wh || (rhi == wh && rlo > wl)) { wh = rhi; wl = rlo; }
        if (lane == 0) s_wkey[w] = ((ull)wh << 32) | wl;
        __syncthreads();                                   // ---- BARRIER 3 ----

        // ---- redundant global argmax over 32 warp partials ----
        const ull k2 = s_wkey[lane];
        const unsigned h2 = (unsigned)(k2 >> 32), l2 = (unsigned)k2;
        const unsigned gv = __reduce_max_sync(0xFFFFFFFFu, h2);
        const unsigned gl = __reduce_max_sync(0xFFFFFFFFu, (h2 == gv) ? l2 : 0u);

        const int widx = (int)(0xFFFFFFFFu - gl);
        cx = __ldg(obase + widx * 3 + 0);                   // broadcast, L1-hot
        cy = __ldg(obase + widx * 3 + 1);
        cz = __ldg(obase + widx * 3 + 2);
        if (t == 0) { cen[s * 3 + 0] = cx; cen[s * 3 + 1] = cy; cen[s * 3 + 2] = cz; }
    }
}

// ============================================================================
// Ball query + gather: one warp per centroid, 64 pts per ballot iteration,
// early exit at K hits. First 2048 points cached in SMEM per block; gmem tail.
// Scan order == ascending index == reference top_k order.
// ============================================================================
#define BQ_WARPS   8
#define BQ_CACHE   2048

__global__ __launch_bounds__(BQ_WARPS * 32)
void group_kernel(const float* __restrict__ xyz,
                  const float* __restrict__ feat,
                  float* __restrict__ out)
{
    __shared__ float s_pts[BQ_CACHE * 3];
    __shared__ int   s_idx[BQ_WARPS][K_NB];

    const int tid  = threadIdx.x;
    const int w    = tid >> 5;
    const int lane = tid & 31;
    const int c    = blockIdx.x * BQ_WARPS + w;          // centroid id
    const int b    = c >> 10;                            // 128 blocks per batch
    const float* base = xyz + (size_t)b * N_PTS * 3;

    for (int i = tid; i < BQ_CACHE * 3; i += BQ_WARPS * 32) s_pts[i] = base[i];
    __syncthreads();

    const float* cen = out + CEN_OFF + (size_t)c * 3;
    const float cx = __ldg(cen + 0), cy = __ldg(cen + 1), cz = __ldg(cen + 2);
    const float R2 = (float)(0.2 * 0.2);

    int cnt = 0;
    for (int j = 0; j < BQ_CACHE / 64 && cnt < K_NB; ++j) {
        const int p0 = j * 64 + lane;
        const int p1 = p0 + 32;
        const float dx0 = __fadd_rn(cx, -s_pts[p0 * 3 + 0]);
        const float dy0 = __fadd_rn(cy, -s_pts[p0 * 3 + 1]);
        const float dz0 = __fadd_rn(cz, -s_pts[p0 * 3 + 2]);
        const float sq0 = __fadd_rn(__fadd_rn(__fmul_rn(dx0, dx0), __fmul_rn(dy0, dy0)),
                                    __fmul_rn(dz0, dz0));
        const float dx1 = __fadd_rn(cx, -s_pts[p1 * 3 + 0]);
        const float dy1 = __fadd_rn(cy, -s_pts[p1 * 3 + 1]);
        const float dz1 = __fadd_rn(cz, -s_pts[p1 * 3 + 2]);
        const float sq1 = __fadd_rn(__fadd_rn(__fmul_rn(dx1, dx1), __fmul_rn(dy1, dy1)),
                                    __fmul_rn(dz1, dz1));
        const bool h0 = (sq0 <= R2);
        const bool h1 = (sq1 <= R2);
        const unsigned m0 = __ballot_sync(0xFFFFFFFFu, h0);
        const unsigned m1 = __ballot_sync(0xFFFFFFFFu, h1);
        if (h0) {
            const int pos = cnt + __popc(m0 & ((1u << lane) - 1u));
            if (pos < K_NB) s_idx[w][pos] = p0;
        }
        const int c1 = cnt + __popc(m0);
        if (h1) {
            const int pos = c1 + __popc(m1 & ((1u << lane) - 1u));
            if (pos < K_NB) s_idx[w][pos] = p1;
        }
        cnt = c1 + __popc(m1);
    }
    for (int j = BQ_CACHE / 64; j < N_PTS / 64 && cnt < K_NB; ++j) {
        const int p0 = j * 64 + lane;
        const int p1 = p0 + 32;
        const float dx0 = __fadd_rn(cx, -base[p0 * 3 + 0]);
        const float dy0 = __fadd_rn(cy, -base[p0 * 3 + 1]);
        const float dz0 = __fadd_rn(cz, -base[p0 * 3 + 2]);
        const float sq0 = __fadd_rn(__fadd_rn(__fmul_rn(dx0, dx0), __fmul_rn(dy0, dy0)),
                                    __fmul_rn(dz0, dz0));
        const float dx1 = __fadd_rn(cx, -base[p1 * 3 + 0]);
        const float dy1 = __fadd_rn(cy, -base[p1 * 3 + 1]);
        const float dz1 = __fadd_rn(cz, -base[p1 * 3 + 2]);
        const float sq1 = __fadd_rn(__fadd_rn(__fmul_rn(dx1, dx1), __fmul_rn(dy1, dy1)),
                                    __fmul_rn(dz1, dz1));
        const bool h0 = (sq0 <= R2);
        const bool h1 = (sq1 <= R2);
        const unsigned m0 = __ballot_sync(0xFFFFFFFFu, h0);
        const unsigned m1 = __ballot_sync(0xFFFFFFFFu, h1);
        if (h0) {
            const int pos = cnt + __popc(m0 & ((1u << lane) - 1u));
            if (pos < K_NB) s_idx[w][pos] = p0;
        }
        const int c1 = cnt + __popc(m0);
        if (h1) {
            const int pos = c1 + __popc(m1 & ((1u << lane) - 1u));
            if (pos < K_NB) s_idx[w][pos] = p1;
        }
        cnt = c1 + __popc(m1);
    }
    __syncwarp();
    const int first = s_idx[w][0];          // >=1 hit guaranteed (centroid itself)
    if (cnt < K_NB && lane >= cnt) s_idx[w][lane] = first;
    __syncwarp();

    {
        const int gi = s_idx[w][lane];
        float* go = out + GX_OFF + ((size_t)c * K_NB + lane) * 3;
        go[0] = __fadd_rn(base[gi * 3 + 0], -cx);
        go[1] = __fadd_rn(base[gi * 3 + 1], -cy);
        go[2] = __fadd_rn(base[gi * 3 + 2], -cz);
    }

    const float4* f4 = (const float4*)feat;
    float4* o4 = (float4*)(out + GF_OFF) + (size_t)c * K_NB * (C_FEAT / 4);
#pragma unroll 4
    for (int k = 0; k < K_NB; ++k) {
        const int gi = s_idx[w][k];
        o4[(size_t)k * (C_FEAT / 4) + lane] =
            f4[((size_t)b * N_PTS + gi) * (C_FEAT / 4) + lane];
    }
}

// ============================================================================
extern "C" void kernel_launch(void* const* d_in, const int* in_sizes, int n_in,
                              void* d_out, int out_size)
{
    const float* xyz  = (const float*)d_in[0];
    const float* feat = (const float*)d_in[1];
    if (n_in >= 2 && in_sizes[0] > in_sizes[1]) {   // defensive: xyz is smaller
        const float* tmp = xyz; xyz = feat; feat = tmp;
    }
    float* out = (float*)d_out;

    const int fps_smem = N_PTS * 4;     // min_d
    cudaFuncSetAttribute(fps_kernel, cudaFuncAttributeMaxDynamicSharedMemorySize,
                         fps_smem);

    sort_kernel<<<B_SZ, 1024>>>(xyz);
    fps_kernel<<<B_SZ, FPS_T, fps_smem>>>(xyz, out);
    group_kernel<<<(B_SZ * S_SAMPLES) / BQ_WARPS, BQ_WARPS * 32>>>(xyz, feat, out);
}